// round 1
// baseline (speedup 1.0000x reference)
#include <cuda_runtime.h>
#include <cuda_bf16.h>

#define NB_MAX   16
#define CDIM     256
#define GEM_EPSF 1e-6f
#define NORM_EPSF 1e-12f

// Scratch (allocation-free): per-(batch,channel) sums and per-batch counts.
__device__ float g_sums[NB_MAX * CDIM];
__device__ float g_counts[NB_MAX];

__global__ void mink_zero() {
    int t = threadIdx.x;
    for (int k = t; k < NB_MAX * CDIM; k += blockDim.x) g_sums[k] = 0.0f;
    if (t < NB_MAX) g_counts[t] = 0.0f;
}

// Row-range accumulation. Each thread owns channel `tid`. Sorted batch_idx:
// register accumulator per current segment, flush to smem on segment change.
template <bool CUBE>
__device__ __forceinline__ void accum_rows(
    const float* __restrict__ feat, const int* __restrict__ bidx,
    int r0, int r1, int tid, float pv, float* s_acc)
{
    float acc = 0.0f;
    int   cur_b = bidx[r0];
    int   cnt = 0;

    int r = r0;
    for (; r + 8 <= r1; r += 8) {
        // sorted => endpoints equal implies whole chunk in one segment
        if (bidx[r] == cur_b && bidx[r + 7] == cur_b) {
            float v[8];
            #pragma unroll
            for (int u = 0; u < 8; ++u)
                v[u] = feat[(size_t)(r + u) * CDIM + tid];
            #pragma unroll
            for (int u = 0; u < 8; ++u) {
                float x = fmaxf(v[u], GEM_EPSF);
                acc += CUBE ? x * x * x : powf(x, pv);
            }
            cnt += 8;
        } else {
            #pragma unroll
            for (int u = 0; u < 8; ++u) {
                int b = bidx[r + u];
                if (b != cur_b) {
                    s_acc[cur_b * CDIM + tid] += acc;
                    acc = 0.0f;
                    if (tid == 0) atomicAdd(&g_counts[cur_b], (float)cnt);
                    cnt = 0;
                    cur_b = b;
                }
                float x = fmaxf(feat[(size_t)(r + u) * CDIM + tid], GEM_EPSF);
                acc += CUBE ? x * x * x : powf(x, pv);
                ++cnt;
            }
        }
    }
    for (; r < r1; ++r) {
        int b = bidx[r];
        if (b != cur_b) {
            s_acc[cur_b * CDIM + tid] += acc;
            acc = 0.0f;
            if (tid == 0) atomicAdd(&g_counts[cur_b], (float)cnt);
            cnt = 0;
            cur_b = b;
        }
        float x = fmaxf(feat[(size_t)r * CDIM + tid], GEM_EPSF);
        acc += CUBE ? x * x * x : powf(x, pv);
        ++cnt;
    }
    s_acc[cur_b * CDIM + tid] += acc;
    if (tid == 0) atomicAdd(&g_counts[cur_b], (float)cnt);
}

__global__ void __launch_bounds__(CDIM) mink_accum(
    const float* __restrict__ feat, const float* __restrict__ p,
    const int* __restrict__ bidx, int n)
{
    __shared__ float s_acc[NB_MAX * CDIM];
    int tid = threadIdx.x;
    #pragma unroll
    for (int k = tid; k < NB_MAX * CDIM; k += CDIM) s_acc[k] = 0.0f;
    __syncthreads();

    int rpb = (n + (int)gridDim.x - 1) / (int)gridDim.x;
    int r0  = (int)blockIdx.x * rpb;
    int r1  = min(n, r0 + rpb);
    if (r0 < r1) {
        float pv = p[0];
        if (pv == 3.0f) accum_rows<true >(feat, bidx, r0, r1, tid, pv, s_acc);
        else            accum_rows<false>(feat, bidx, r0, r1, tid, pv, s_acc);
    }
    __syncthreads();

    #pragma unroll
    for (int b = 0; b < NB_MAX; ++b) {
        float v = s_acc[b * CDIM + tid];
        if (v != 0.0f) atomicAdd(&g_sums[b * CDIM + tid], v);
    }
}

__global__ void __launch_bounds__(CDIM) mink_finalize(
    const float* __restrict__ p, float* __restrict__ out, int nb)
{
    __shared__ float red[CDIM];
    int tid = threadIdx.x;
    float invp = 1.0f / p[0];

    for (int b = 0; b < nb; ++b) {
        float c    = g_counts[b];
        float mean = (c > 0.0f) ? g_sums[b * CDIM + tid] / c : 0.0f;
        float desc = powf(mean, invp);   // mean >= eps^p > 0 when c>0; powf(0,invp)=0
        red[tid] = desc * desc;
        __syncthreads();
        #pragma unroll
        for (int s = CDIM / 2; s > 0; s >>= 1) {
            if (tid < s) red[tid] += red[tid + s];
            __syncthreads();
        }
        float norm = sqrtf(red[0]);
        out[b * CDIM + tid] = desc / fmaxf(norm, NORM_EPSF);
        __syncthreads();
    }
}

extern "C" void kernel_launch(void* const* d_in, const int* in_sizes, int n_in,
                              void* d_out, int out_size)
{
    const float* feat = (const float*)d_in[0];
    const float* p    = (const float*)d_in[1];
    const int*   bidx = (const int*)d_in[2];
    // d_in[3] = num_batches (device scalar) — derived host-side from out_size instead.

    int n  = in_sizes[2];                 // N voxels
    int nb = out_size / CDIM;             // B point clouds
    if (nb > NB_MAX) nb = NB_MAX;

    mink_zero<<<1, 256>>>();

    int grid = 148 * 8;                   // one full wave at 256 thr/block
    if (grid > (n + 7) / 8) grid = (n + 7) / 8;
    if (grid < 1) grid = 1;
    mink_accum<<<grid, CDIM>>>(feat, p, bidx, n);

    mink_finalize<<<1, CDIM>>>(p, (float*)d_out, nb);
}

// round 2
// speedup vs baseline: 1.1321x; 1.1321x over previous
#include <cuda_runtime.h>
#include <cuda_bf16.h>

#define NB_MAX    16
#define CDIM      256
#define GEM_EPSF  1e-6f
#define NORM_EPSF 1e-12f
#define CHUNK     32

// Scratch (allocation-free). Zeroed at module load; finalize re-zeroes after
// use, so the "zeroed before accum" invariant holds across graph replays.
__device__ float g_sums[NB_MAX * CDIM];
__device__ float g_counts[NB_MAX];

template <bool CUBE>
__device__ __forceinline__ float gem1(float x, float pv) {
    float v = fmaxf(x, GEM_EPSF);
    return CUBE ? v * v * v : powf(v, pv);
}

__device__ __forceinline__ void flush_acc(
    float* s_acc, float* s_cnt, int cur_b, int c4,
    float4& acc, int& cnt)
{
    float* dst = s_acc + cur_b * CDIM + 4 * c4;
    if (acc.x != 0.0f || acc.y != 0.0f || acc.z != 0.0f || acc.w != 0.0f) {
        atomicAdd(dst + 0, acc.x);
        atomicAdd(dst + 1, acc.y);
        atomicAdd(dst + 2, acc.z);
        atomicAdd(dst + 3, acc.w);
        acc = make_float4(0.f, 0.f, 0.f, 0.f);
    }
    if (c4 == 0 && cnt) atomicAdd(&s_cnt[cur_b], (float)cnt);
    cnt = 0;
}

// Core accumulation over this block's row range. Thread (rg = tid>>6,
// c4 = tid&63) owns channels 4*c4..4*c4+3 and rows congruent to rg mod 4.
template <bool CUBE>
__device__ __forceinline__ void accum_range(
    const float4* __restrict__ feat4, const int* __restrict__ bidx,
    int r0, int r1, int c4, int rg, float pv, float* s_acc, float* s_cnt)
{
    float4 acc = make_float4(0.f, 0.f, 0.f, 0.f);
    int cnt = 0;
    int cur_b = bidx[r0];
    int r = r0;

    for (; r + CHUNK <= r1; r += CHUNK) {
        // sorted batch_idx: equal endpoints => whole chunk in one segment
        if (bidx[r] == cur_b && bidx[r + CHUNK - 1] == cur_b) {
            float4 v[8];
            #pragma unroll
            for (int k = 0; k < 8; ++k)
                v[k] = feat4[(size_t)(r + 4 * k + rg) * (CDIM / 4) + c4];
            #pragma unroll
            for (int k = 0; k < 8; ++k) {
                acc.x += gem1<CUBE>(v[k].x, pv);
                acc.y += gem1<CUBE>(v[k].y, pv);
                acc.z += gem1<CUBE>(v[k].z, pv);
                acc.w += gem1<CUBE>(v[k].w, pv);
            }
            cnt += 8;   // rows handled by THIS thread in this chunk
        } else {
            // per-row slow path (uniform branch: depends only on shared bidx)
            for (int rr = r; rr < r + CHUNK; ++rr) {
                int b = bidx[rr];
                if (b != cur_b) {
                    flush_acc(s_acc, s_cnt, cur_b, c4, acc, cnt);
                    cur_b = b;
                }
                if (rg == (rr & 3)) {
                    float4 x = feat4[(size_t)rr * (CDIM / 4) + c4];
                    acc.x += gem1<CUBE>(x.x, pv);
                    acc.y += gem1<CUBE>(x.y, pv);
                    acc.z += gem1<CUBE>(x.z, pv);
                    acc.w += gem1<CUBE>(x.w, pv);
                    ++cnt;
                }
            }
        }
    }
    for (; r < r1; ++r) {               // tail rows
        int b = bidx[r];
        if (b != cur_b) {
            flush_acc(s_acc, s_cnt, cur_b, c4, acc, cnt);
            cur_b = b;
        }
        if (rg == (r & 3)) {
            float4 x = feat4[(size_t)r * (CDIM / 4) + c4];
            acc.x += gem1<CUBE>(x.x, pv);
            acc.y += gem1<CUBE>(x.y, pv);
            acc.z += gem1<CUBE>(x.z, pv);
            acc.w += gem1<CUBE>(x.w, pv);
            ++cnt;
        }
    }
    flush_acc(s_acc, s_cnt, cur_b, c4, acc, cnt);
}

__global__ void __launch_bounds__(256, 4) mink_accum(
    const float4* __restrict__ feat4, const float* __restrict__ p,
    const int* __restrict__ bidx, int n, int rpb)
{
    __shared__ float s_acc[NB_MAX * CDIM];
    __shared__ float s_cnt[NB_MAX];
    const int tid = threadIdx.x;
    const int c4  = tid & 63;
    const int rg  = tid >> 6;

    #pragma unroll
    for (int k = tid; k < NB_MAX * CDIM; k += 256) s_acc[k] = 0.0f;
    if (tid < NB_MAX) s_cnt[tid] = 0.0f;
    __syncthreads();

    const int r0 = (int)blockIdx.x * rpb;
    const int r1 = min(n, r0 + rpb);
    if (r0 < r1) {
        const float pv = p[0];
        if (pv == 3.0f)
            accum_range<true >(feat4, bidx, r0, r1, c4, rg, pv, s_acc, s_cnt);
        else
            accum_range<false>(feat4, bidx, r0, r1, c4, rg, pv, s_acc, s_cnt);
    }
    __syncthreads();

    #pragma unroll
    for (int b = 0; b < NB_MAX; ++b) {
        float v = s_acc[b * CDIM + tid];
        if (v != 0.0f) atomicAdd(&g_sums[b * CDIM + tid], v);
    }
    if (tid < NB_MAX && s_cnt[tid] != 0.0f) atomicAdd(&g_counts[tid], s_cnt[tid]);
}

__global__ void __launch_bounds__(CDIM) mink_finalize(
    const float* __restrict__ p, float* __restrict__ out, int nb)
{
    __shared__ float red[CDIM];
    const int tid = threadIdx.x;
    const float invp = 1.0f / p[0];

    for (int b = 0; b < nb; ++b) {
        float c    = g_counts[b];
        float mean = (c > 0.0f) ? g_sums[b * CDIM + tid] / c : 0.0f;
        float desc = powf(mean, invp);   // mean >= eps^p > 0 when c>0
        red[tid] = desc * desc;
        __syncthreads();
        #pragma unroll
        for (int s = CDIM / 2; s > 0; s >>= 1) {
            if (tid < s) red[tid] += red[tid + s];
            __syncthreads();
        }
        float norm = sqrtf(red[0]);
        out[b * CDIM + tid] = desc / fmaxf(norm, NORM_EPSF);
        __syncthreads();
    }

    // Restore scratch to zero for the next call / graph replay.
    #pragma unroll
    for (int k = tid; k < NB_MAX * CDIM; k += CDIM) g_sums[k] = 0.0f;
    if (tid < NB_MAX) g_counts[tid] = 0.0f;
}

extern "C" void kernel_launch(void* const* d_in, const int* in_sizes, int n_in,
                              void* d_out, int out_size)
{
    const float4* feat4 = (const float4*)d_in[0];
    const float*  p     = (const float*)d_in[1];
    const int*    bidx  = (const int*)d_in[2];

    int n  = in_sizes[2];          // N voxels
    int nb = out_size / CDIM;      // B point clouds
    if (nb > NB_MAX) nb = NB_MAX;

    // One wave: 148 SMs x 4 blocks/SM (64-reg budget). Rows/block rounded to
    // CHUNK so the wide fast path dominates.
    const int target = 148 * 4;
    int rpb = (n + target - 1) / target;
    rpb = (rpb + CHUNK - 1) & ~(CHUNK - 1);
    if (rpb < CHUNK) rpb = CHUNK;
    int grid = (n + rpb - 1) / rpb;

    mink_accum<<<grid, 256>>>(feat4, p, bidx, n, rpb);
    mink_finalize<<<1, CDIM>>>(p, (float*)d_out, nb);
}

// round 4
// speedup vs baseline: 1.1618x; 1.0262x over previous
#include <cuda_runtime.h>
#include <cuda_bf16.h>

#define NB_MAX    16
#define CDIM      256
#define GEM_EPSF  1e-6f
#define NORM_EPSF 1e-12f
#define CHUNK     32

// Scratch (allocation-free). Zeroed at module load; the fused finalize tail
// re-zeroes everything after use, so the invariant holds across graph replays.
__device__ float        g_sums[NB_MAX * CDIM];
__device__ float        g_counts[NB_MAX];
__device__ unsigned int g_ticket;

template <bool CUBE>
__device__ __forceinline__ float gem1(float x, float pv) {
    float v = fmaxf(x, GEM_EPSF);
    return CUBE ? v * v * v : powf(v, pv);
}

__device__ __forceinline__ void flush_acc(
    float* s_acc, float* s_cnt, int cur_b, int c4,
    float4& acc, int& cnt)
{
    float* dst = s_acc + cur_b * CDIM + 4 * c4;
    if (acc.x != 0.0f || acc.y != 0.0f || acc.z != 0.0f || acc.w != 0.0f) {
        atomicAdd(dst + 0, acc.x);
        atomicAdd(dst + 1, acc.y);
        atomicAdd(dst + 2, acc.z);
        atomicAdd(dst + 3, acc.w);
        acc = make_float4(0.f, 0.f, 0.f, 0.f);
    }
    if (c4 == 0 && cnt) atomicAdd(&s_cnt[cur_b], (float)cnt);
    cnt = 0;
}

// Core accumulation over this block's row range. Thread (rg = tid>>6,
// c4 = tid&63) owns channels 4*c4..4*c4+3 and rows congruent to rg mod 4.
template <bool CUBE>
__device__ __forceinline__ void accum_range(
    const float4* __restrict__ feat4, const int* __restrict__ bidx,
    int r0, int r1, int c4, int rg, float pv, float* s_acc, float* s_cnt)
{
    float4 acc = make_float4(0.f, 0.f, 0.f, 0.f);
    int cnt = 0;
    int cur_b = bidx[r0];
    int r = r0;

    for (; r + CHUNK <= r1; r += CHUNK) {
        // sorted batch_idx: equal endpoints => whole chunk in one segment
        if (bidx[r] == cur_b && bidx[r + CHUNK - 1] == cur_b) {
            float4 v[8];
            #pragma unroll
            for (int k = 0; k < 8; ++k)
                v[k] = feat4[(size_t)(r + 4 * k + rg) * (CDIM / 4) + c4];
            #pragma unroll
            for (int k = 0; k < 8; ++k) {
                acc.x += gem1<CUBE>(v[k].x, pv);
                acc.y += gem1<CUBE>(v[k].y, pv);
                acc.z += gem1<CUBE>(v[k].z, pv);
                acc.w += gem1<CUBE>(v[k].w, pv);
            }
            cnt += 8;   // rows handled by THIS thread in this chunk
        } else {
            // per-row slow path (uniform branch: depends only on shared bidx)
            for (int rr = r; rr < r + CHUNK; ++rr) {
                int b = bidx[rr];
                if (b != cur_b) {
                    flush_acc(s_acc, s_cnt, cur_b, c4, acc, cnt);
                    cur_b = b;
                }
                if (rg == (rr & 3)) {
                    float4 x = feat4[(size_t)rr * (CDIM / 4) + c4];
                    acc.x += gem1<CUBE>(x.x, pv);
                    acc.y += gem1<CUBE>(x.y, pv);
                    acc.z += gem1<CUBE>(x.z, pv);
                    acc.w += gem1<CUBE>(x.w, pv);
                    ++cnt;
                }
            }
        }
    }
    for (; r < r1; ++r) {               // tail rows
        int b = bidx[r];
        if (b != cur_b) {
            flush_acc(s_acc, s_cnt, cur_b, c4, acc, cnt);
            cur_b = b;
        }
        if (rg == (r & 3)) {
            float4 x = feat4[(size_t)r * (CDIM / 4) + c4];
            acc.x += gem1<CUBE>(x.x, pv);
            acc.y += gem1<CUBE>(x.y, pv);
            acc.z += gem1<CUBE>(x.z, pv);
            acc.w += gem1<CUBE>(x.w, pv);
            ++cnt;
        }
    }
    flush_acc(s_acc, s_cnt, cur_b, c4, acc, cnt);
}

__global__ void __launch_bounds__(256, 4) mink_fused(
    const float4* __restrict__ feat4, const float* __restrict__ p,
    const int* __restrict__ bidx, float* __restrict__ out,
    int n, int rpb, int nb)
{
    __shared__ float s_acc[NB_MAX * CDIM];
    __shared__ float s_cnt[NB_MAX];
    __shared__ unsigned int s_last;
    __shared__ float s_red[8];

    const int tid = threadIdx.x;
    const int c4  = tid & 63;
    const int rg  = tid >> 6;

    #pragma unroll
    for (int k = tid; k < NB_MAX * CDIM; k += 256) s_acc[k] = 0.0f;
    if (tid < NB_MAX) s_cnt[tid] = 0.0f;
    __syncthreads();

    const float pv = p[0];
    const int r0 = (int)blockIdx.x * rpb;
    const int r1 = min(n, r0 + rpb);
    if (r0 < r1) {
        if (pv == 3.0f)
            accum_range<true >(feat4, bidx, r0, r1, c4, rg, pv, s_acc, s_cnt);
        else
            accum_range<false>(feat4, bidx, r0, r1, c4, rg, pv, s_acc, s_cnt);
    }
    __syncthreads();

    // Block -> global (skip zero entries: most blocks touch 1-2 batches).
    #pragma unroll
    for (int b = 0; b < NB_MAX; ++b) {
        float v = s_acc[b * CDIM + tid];
        if (v != 0.0f) atomicAdd(&g_sums[b * CDIM + tid], v);
    }
    if (tid < NB_MAX && s_cnt[tid] != 0.0f) atomicAdd(&g_counts[tid], s_cnt[tid]);

    // ---- last-block finalize (threadFenceReduction pattern) ----
    __threadfence();                 // release: my global sums visible pre-ticket
    __syncthreads();
    if (tid == 0) {
        unsigned int t = atomicAdd(&g_ticket, 1u);
        s_last = (t == gridDim.x - 1) ? 1u : 0u;
    }
    __syncthreads();
    if (s_last == 0u) return;
    __threadfence();                 // acquire: order subsequent reads after ticket

    // All blocks' atomics have landed at L2. Read with L1 bypass.
    const float invp = 1.0f / pv;
    const int lane = tid & 31, warp = tid >> 5;

    float sums[NB_MAX], cnts[NB_MAX];
    #pragma unroll
    for (int b = 0; b < NB_MAX; ++b)                  // MLP=16: all loads first
        sums[b] = __ldcg(&g_sums[b * CDIM + tid]);
    #pragma unroll
    for (int b = 0; b < NB_MAX; ++b)
        cnts[b] = (b < nb) ? __ldcg(&g_counts[b]) : 0.0f;

    #pragma unroll
    for (int b = 0; b < NB_MAX; ++b) {
        if (b >= nb) break;
        float c    = cnts[b];
        float mean = (c > 0.0f) ? sums[b] / c : 0.0f;
        float desc = powf(mean, invp);   // mean >= eps^p > 0 when c>0
        float sq   = desc * desc;
        #pragma unroll
        for (int m = 16; m > 0; m >>= 1)               // warp butterfly
            sq += __shfl_xor_sync(0xffffffffu, sq, m);
        if (lane == 0) s_red[warp] = sq;
        __syncthreads();
        float tot = s_red[0] + s_red[1] + s_red[2] + s_red[3]
                  + s_red[4] + s_red[5] + s_red[6] + s_red[7];
        out[b * CDIM + tid] = desc / fmaxf(sqrtf(tot), NORM_EPSF);
        __syncthreads();
    }

    // Reset scratch for the next call / graph replay.
    #pragma unroll
    for (int k = tid; k < NB_MAX * CDIM; k += 256) g_sums[k] = 0.0f;
    if (tid < NB_MAX) g_counts[tid] = 0.0f;
    if (tid == 0) g_ticket = 0u;
}

extern "C" void kernel_launch(void* const* d_in, const int* in_sizes, int n_in,
                              void* d_out, int out_size)
{
    const float4* feat4 = (const float4*)d_in[0];
    const float*  p     = (const float*)d_in[1];
    const int*    bidx  = (const int*)d_in[2];

    int n  = in_sizes[2];          // N voxels
    int nb = out_size / CDIM;      // B point clouds
    if (nb > NB_MAX) nb = NB_MAX;

    // One wave: 148 SMs x 4 blocks/SM. Rows/block rounded to CHUNK so the
    // wide fast path dominates.
    const int target = 148 * 4;
    int rpb = (n + target - 1) / target;
    rpb = (rpb + CHUNK - 1) & ~(CHUNK - 1);
    if (rpb < CHUNK) rpb = CHUNK;
    int grid = (n + rpb - 1) / rpb;

    mink_fused<<<grid, 256>>>(feat4, p, bidx, (float*)d_out, n, rpb, nb);
}